// round 11
// baseline (speedup 1.0000x reference)
#include <cuda_runtime.h>
#include <cstdint>

typedef unsigned long long u64;

#define BATCH 16
#define CHAN  256
#define H     64
#define W     64
#define HW    (H * W)
#define MAXD  4
#define PATCH 9
#define ITILE 4

#define CC      4                  // channels per pipeline stage
#define NCHUNK  (CHAN / CC)        // 64
#define STAGES  3
#define YROWS   (ITILE + 2*MAXD)   // 12
#define YPITCH  72                 // 4 pad + 64 + 4 pad (18 units)
#define XCH     (ITILE * W)        // 256 floats per channel
#define XS      (CC * XCH)         // 1024 floats
#define YCH     (YROWS * YPITCH)   // 864 floats per channel
#define BUFF    (XS + CC * YCH)    // 4480 floats per stage
#define NELEM   1024               // 256 x-units + 768 y-units per chunk

__device__ __forceinline__ int swz(int u) { return u ^ ((u >> 3) & 1); }

__device__ __forceinline__ u64 pack2(float lo, float hi) {
    u64 d; asm("mov.b64 %0, {%1,%2};" : "=l"(d) : "f"(lo), "f"(hi)); return d;
}
__device__ __forceinline__ void unpack2(u64 v, float &lo, float &hi) {
    asm("mov.b64 {%0,%1}, %2;" : "=f"(lo), "=f"(hi) : "l"(v));
}
__device__ __forceinline__ void ffma2(u64 &d, u64 a, u64 b) {
    asm("fma.rn.f32x2 %0, %1, %2, %0;" : "+l"(d) : "l"(a), "l"(b));
}

// Block: (b, i0) tile of 4 rows. 9 warps, warp = di.
// lane: il = lane>>3 (row 0..3), jseg = lane&7 -> 8 px j0..j0+7, all 9 dj.
// Even dj via f32x2 (aligned-pair operands, 20 u64 accs);
// odd dj via scalar FFMA into 32 unpaired f32 accs (no pack pressure).
__global__ __launch_bounds__(288, 2)
void corr_kernel(const float* __restrict__ x,
                 const float* __restrict__ y,
                 float* __restrict__ out)
{
    __shared__ float smem[STAGES][BUFF];

    const int tid  = threadIdx.x;
    const int b    = blockIdx.x >> 4;
    const int i0   = (blockIdx.x & 15) * ITILE;
    const int di   = tid >> 5;
    const int lane = tid & 31;
    const int il   = lane >> 3;
    const int jseg = lane & 7;
    const int j0   = jseg * 8;
    const int i    = i0 + il;

    // ---- zero static y pads (units 0 and 17 of each row, all stages) ----
    for (int z = tid; z < STAGES * CC * YROWS * 8; z += 288) {
        int st  = z / (CC * YROWS * 8);
        int r1  = z - st * (CC * YROWS * 8);
        int ch  = r1 / (YROWS * 8);
        int r2  = r1 - ch * (YROWS * 8);
        int row = r2 >> 3;
        int p   = r2 & 7;
        int col = (p < 4) ? p : (64 + p);
        smem[st][XS + ch * YCH + row * YPITCH + col] = 0.f;
    }

    // ---- cp.async fill slots: 1024 = 160*4 + 128*3 ----
    const int nslot = (tid < 160) ? 4 : 3;
    uint32_t     s_off[4];
    const float* g_ptr[4];
    uint32_t     szbits = 0;          // bit s: slot s copies 16B (else zfill)
    {
        const float* xb = x + ((size_t)b * CHAN) * HW + (size_t)i0 * W;
        const float* yb = y + ((size_t)b * CHAN) * HW;
        #pragma unroll
        for (int s = 0; s < 4; s++) {
            int e = tid + s * 288;
            if (e >= NELEM) e = 0;                // dead slot (never issued)
            if (e < 256) {                        // x unit
                int ch = e >> 6, r = (e >> 4) & 3, u = e & 15;
                s_off[s] = (uint32_t)((ch * XCH + r * W + swz(u) * 4) * 4);
                g_ptr[s] = xb + ch * HW + r * W + u * 4;
                szbits |= 1u << s;
            } else {                              // y interior unit (1..16)
                int e2 = e - 256;
                int ch = e2 / 192, rem = e2 - ch * 192;
                int row = rem >> 4, ui = (rem & 15) + 1;
                int yr = i0 - MAXD + row;
                bool v = (yr >= 0) && (yr < H);
                s_off[s] = (uint32_t)((XS + ch * YCH + row * YPITCH + swz(ui) * 4) * 4);
                g_ptr[s] = yb + ch * HW + (v ? yr : 0) * W + (ui - 1) * 4;
                if (v) szbits |= 1u << s;
            }
        }
    }

    const uint32_t sm0 = (uint32_t)__cvta_generic_to_shared(&smem[0][0]);
    auto do_fill = [&](int st) {
        uint32_t base = sm0 + (uint32_t)st * (BUFF * 4);
        #pragma unroll
        for (int s = 0; s < 4; s++) {
            if (s < nslot) {
                uint32_t sz = ((szbits >> s) & 1u) ? 16u : 0u;
                asm volatile("cp.async.cg.shared.global [%0], [%1], 16, %2;"
                             :: "r"(base + s_off[s]), "l"(g_ptr[s]), "r"(sz));
                g_ptr[s] += CC * HW;
            }
        }
    };

    // ---- per-thread LDS offsets (floats within stage buffer) ----
    const int xrow = il * W;                         // + ch*XCH
    const int yrow = XS + (il + di) * YPITCH;        // + ch*YCH
    const int xu0 = swz(2 * jseg) * 4, xu1 = swz(2 * jseg + 1) * 4;
    int yu[4];
    #pragma unroll
    for (int g = 0; g < 4; g++) yu[g] = swz(2 * jseg + g) * 4;

    // ---- accumulators: 20 u64 (even dj) + 32 f32 (odd dj) = 72 regs ----
    u64 accE[20];
    float accD[4][8];
    #pragma unroll
    for (int m = 0; m < 20; m++) accE[m] = 0ull;
    #pragma unroll
    for (int o = 0; o < 4; o++)
        #pragma unroll
        for (int j = 0; j < 8; j++) accD[o][j] = 0.f;

    __syncthreads();   // pads visible before first compute

    do_fill(0);
    asm volatile("cp.async.commit_group;" ::: "memory");
    do_fill(1);
    asm volatile("cp.async.commit_group;" ::: "memory");

    #pragma unroll 1
    for (int k = 0; k < NCHUNK; k++) {
        asm volatile("cp.async.wait_group 1;" ::: "memory");
        __syncthreads();   // stage k published; stage k-1 free everywhere
        if (k + 2 < NCHUNK) do_fill((k + 2) % STAGES);
        asm volatile("cp.async.commit_group;" ::: "memory");

        const float* B = &smem[k % STAGES][0];
        #pragma unroll
        for (int ch = 0; ch < CC; ch++) {
            const float* xs = B + ch * XCH + xrow;
            const float* ys = B + ch * YCH + yrow;

            float4 x0 = *reinterpret_cast<const float4*>(xs + xu0);
            float4 x1 = *reinterpret_cast<const float4*>(xs + xu1);
            // aligned pairs straight out of the LDS.128 quads (0-MOV packs)
            u64 XE0 = pack2(x0.x, x0.y);
            u64 XE1 = pack2(x0.z, x0.w);
            u64 XE2 = pack2(x1.x, x1.y);
            u64 XE3 = pack2(x1.z, x1.w);
            const float xf[8] = { x0.x, x0.y, x0.z, x0.w,
                                  x1.x, x1.y, x1.z, x1.w };

            // stream y quad-by-quad: quad g = window floats 4g..4g+3
            #pragma unroll
            for (int g = 0; g < 4; g++) {
                float4 q = *reinterpret_cast<const float4*>(ys + yu[g]);
                u64 Plo = pack2(q.x, q.y);     // window pair 2g
                u64 Phi = pack2(q.z, q.w);     // window pair 2g+1
                const float qf[4] = { q.x, q.y, q.z, q.w };

                // even dj=2e: accE[e*4+t] += XE[t] * pair(t+e)
                #pragma unroll
                for (int e = 0; e < 5; e++)
                    #pragma unroll
                    for (int t = 0; t < 4; t++) {
                        u64 xe = (t == 0) ? XE0 : (t == 1) ? XE1 : (t == 2) ? XE2 : XE3;
                        if (t + e == 2 * g)     ffma2(accE[e * 4 + t], xe, Plo);
                        if (t + e == 2 * g + 1) ffma2(accE[e * 4 + t], xe, Phi);
                    }
                // odd dj=2o+1: window float w = 4g+c: accD[o][w-d] += x[w-d]*q[c]
                #pragma unroll
                for (int c = 0; c < 4; c++) {
                    const int w = 4 * g + c;
                    #pragma unroll
                    for (int o = 0; o < 4; o++) {
                        const int j = w - (2 * o + 1);
                        if (j >= 0 && j < 8)
                            accD[o][j] = fmaf(xf[j], qf[c], accD[o][j]);
                    }
                }
            }
        }
    }

    // ---- epilogue: scale by 1/C, two float4 stores per dj ----
    const float inv = 1.0f / (float)CHAN;
    float* ob = out + (((size_t)b * (PATCH * PATCH) + (size_t)di * PATCH) * H + i) * W + j0;
    #pragma unroll
    for (int dj = 0; dj < PATCH; dj++) {
        float v[8];
        if ((dj & 1) == 0) {
            const int e = dj >> 1;
            #pragma unroll
            for (int t = 0; t < 4; t++) unpack2(accE[e * 4 + t], v[2 * t], v[2 * t + 1]);
        } else {
            const int o = dj >> 1;
            #pragma unroll
            for (int j = 0; j < 8; j++) v[j] = accD[o][j];
        }
        float4 lo = make_float4(v[0] * inv, v[1] * inv, v[2] * inv, v[3] * inv);
        float4 hi = make_float4(v[4] * inv, v[5] * inv, v[6] * inv, v[7] * inv);
        *reinterpret_cast<float4*>(ob)     = lo;
        *reinterpret_cast<float4*>(ob + 4) = hi;
        ob += HW;
    }
}

extern "C" void kernel_launch(void* const* d_in, const int* in_sizes, int n_in,
                              void* d_out, int out_size)
{
    const float* x = (const float*)d_in[0];
    const float* y = (const float*)d_in[1];
    float* out = (float*)d_out;
    dim3 grid(BATCH * (H / ITILE));   // 256 blocks -> single wave at occ 2
    dim3 block(32 * PATCH);           // 288 threads = 9 warps
    corr_kernel<<<grid, block>>>(x, y, out);
}

// round 13
// speedup vs baseline: 2.0266x; 2.0266x over previous
#include <cuda_runtime.h>
#include <cstdint>

typedef unsigned long long u64;

#define BATCH 16
#define CHAN  256
#define H     64
#define W     64
#define HW    (H * W)
#define MAXD  4
#define PATCH 9
#define ITILE 4

#define CC      4                  // channels per pipeline stage
#define NCHUNK  (CHAN / CC)        // 64
#define STAGES  4
#define YROWS   (ITILE + 2*MAXD)   // 12
#define YPITCH  72                 // 4 pad + 64 + 4 pad (18 units)
#define XCH     (ITILE * W)        // 256 floats per channel
#define XS      (CC * XCH)         // 1024 floats
#define YCH     (YROWS * YPITCH)   // 864 floats per channel
#define BUFF    (XS + CC * YCH)    // 4480 floats per stage
#define NELEM   1024               // 256 x-units + 768 y-units per chunk

__device__ __forceinline__ int swz(int u) { return u ^ ((u >> 3) & 1); }

__device__ __forceinline__ u64 pack2(float lo, float hi) {
    u64 d; asm("mov.b64 %0, {%1,%2};" : "=l"(d) : "f"(lo), "f"(hi)); return d;
}
__device__ __forceinline__ void unpack2(u64 v, float &lo, float &hi) {
    asm("mov.b64 {%0,%1}, %2;" : "=f"(lo), "=f"(hi) : "l"(v));
}
__device__ __forceinline__ void ffma2(u64 &d, u64 a, u64 b) {
    asm("fma.rn.f32x2 %0, %1, %2, %0;" : "+l"(d) : "l"(a), "l"(b));
}

// Block: (b, i0) tile of 4 rows. 9 warps, warp = di.
// lane: il = lane>>3 (row 0..3), jseg = lane&7, thread owns 8 px, all 9 dj.
// Occupancy 1: full register file per CTA -> 72 accs live with zero spill.
__global__ __launch_bounds__(288, 1)
void corr_kernel(const float* __restrict__ x,
                 const float* __restrict__ y,
                 float* __restrict__ out)
{
    __shared__ float smem[STAGES][BUFF];

    const int tid  = threadIdx.x;
    const int b    = blockIdx.x >> 4;
    const int i0   = (blockIdx.x & 15) * ITILE;
    const int di   = tid >> 5;
    const int lane = tid & 31;
    const int il   = lane >> 3;
    const int jseg = lane & 7;
    const int j0   = jseg * 8;
    const int i    = i0 + il;

    // ---- zero static y pads (units 0 and 17 of each row, all stages) ----
    for (int z = tid; z < STAGES * CC * YROWS * 8; z += 288) {
        int st  = z / (CC * YROWS * 8);
        int r1  = z - st * (CC * YROWS * 8);
        int ch  = r1 / (YROWS * 8);
        int r2  = r1 - ch * (YROWS * 8);
        int row = r2 >> 3;
        int p   = r2 & 7;
        int col = (p < 4) ? p : (64 + p);
        smem[st][XS + ch * YCH + row * YPITCH + col] = 0.f;
    }

    // ---- cp.async fill slots: 1024 = 160*4 + 128*3 ----
    const int nslot = (tid < 160) ? 4 : 3;
    uint32_t     s_off[4];
    const float* g_ptr[4];
    uint32_t     szbits = 0;          // bit s: slot s copies 16B (else zfill)
    {
        const float* xb = x + ((size_t)b * CHAN) * HW + (size_t)i0 * W;
        const float* yb = y + ((size_t)b * CHAN) * HW;
        #pragma unroll
        for (int s = 0; s < 4; s++) {
            int e = tid + s * 288;
            if (e >= NELEM) e = 0;                // dead slot (never issued)
            if (e < 256) {                        // x unit
                int ch = e >> 6, r = (e >> 4) & 3, u = e & 15;
                s_off[s] = (uint32_t)((ch * XCH + r * W + swz(u) * 4) * 4);
                g_ptr[s] = xb + ch * HW + r * W + u * 4;
                szbits |= 1u << s;
            } else {                              // y interior unit (1..16)
                int e2 = e - 256;
                int ch = e2 / 192, rem = e2 - ch * 192;
                int row = rem >> 4, ui = (rem & 15) + 1;
                int yr = i0 - MAXD + row;
                bool v = (yr >= 0) && (yr < H);
                s_off[s] = (uint32_t)((XS + ch * YCH + row * YPITCH + swz(ui) * 4) * 4);
                g_ptr[s] = yb + ch * HW + (v ? yr : 0) * W + (ui - 1) * 4;
                if (v) szbits |= 1u << s;
            }
        }
    }

    const uint32_t sm0 = (uint32_t)__cvta_generic_to_shared(&smem[0][0]);
    auto do_fill = [&](int st) {
        uint32_t base = sm0 + (uint32_t)st * (BUFF * 4);
        #pragma unroll
        for (int s = 0; s < 4; s++) {
            if (s < nslot) {
                uint32_t sz = ((szbits >> s) & 1u) ? 16u : 0u;
                asm volatile("cp.async.cg.shared.global [%0], [%1], 16, %2;"
                             :: "r"(base + s_off[s]), "l"(g_ptr[s]), "r"(sz));
                g_ptr[s] += CC * HW;
            }
        }
    };

    // ---- per-thread LDS base offsets (floats within stage buffer) ----
    const int xrow = il * W;                         // + ch*XCH
    const int yrow = XS + (il + di) * YPITCH;        // + ch*YCH
    const int xu0 = swz(2 * jseg) * 4, xu1 = swz(2 * jseg + 1) * 4;
    int yu[4];
    #pragma unroll
    for (int g = 0; g < 4; g++) yu[g] = swz(2 * jseg + g) * 4;

    // ---- accumulators: 32 u64 + 8 f32 = 72 regs (no spill at occ 1) ----
    u64 accE[5][4], accO[4][3];
    float aS0[4], aS7[4];
    #pragma unroll
    for (int e = 0; e < 5; e++)
        #pragma unroll
        for (int t = 0; t < 4; t++) accE[e][t] = 0ull;
    #pragma unroll
    for (int o = 0; o < 4; o++) {
        aS0[o] = 0.f; aS7[o] = 0.f;
        #pragma unroll
        for (int s = 0; s < 3; s++) accO[o][s] = 0ull;
    }

    __syncthreads();   // pads visible before first compute

    do_fill(0);
    asm volatile("cp.async.commit_group;" ::: "memory");
    do_fill(1);
    asm volatile("cp.async.commit_group;" ::: "memory");
    do_fill(2);
    asm volatile("cp.async.commit_group;" ::: "memory");

    #pragma unroll 1
    for (int k = 0; k < NCHUNK; k++) {
        asm volatile("cp.async.wait_group 2;" ::: "memory");
        __syncthreads();   // stage k published; stage k-1 free everywhere
        if (k + 3 < NCHUNK) do_fill((k + 3) % STAGES);
        asm volatile("cp.async.commit_group;" ::: "memory");

        const float* B = &smem[k % STAGES][0];
        #pragma unroll
        for (int ch = 0; ch < CC; ch++) {
            const float* xs = B + ch * XCH + xrow;
            const float* ys = B + ch * YCH + yrow;
            float4 x0 = *reinterpret_cast<const float4*>(xs + xu0);
            float4 x1 = *reinterpret_cast<const float4*>(xs + xu1);
            float4 ya = *reinterpret_cast<const float4*>(ys + yu[0]);
            float4 yb = *reinterpret_cast<const float4*>(ys + yu[1]);
            float4 yc = *reinterpret_cast<const float4*>(ys + yu[2]);
            float4 yd = *reinterpret_cast<const float4*>(ys + yu[3]);

            u64 Pm[8] = { pack2(ya.x, ya.y), pack2(ya.z, ya.w),
                          pack2(yb.x, yb.y), pack2(yb.z, yb.w),
                          pack2(yc.x, yc.y), pack2(yc.z, yc.w),
                          pack2(yd.x, yd.y), pack2(yd.z, yd.w) };
            u64 XE[4] = { pack2(x0.x, x0.y), pack2(x0.z, x0.w),
                          pack2(x1.x, x1.y), pack2(x1.z, x1.w) };

            // even dj = 2e: px pair (2t,2t+1) x q-pair (t+e)
            #pragma unroll
            for (int e = 0; e < 5; e++)
                #pragma unroll
                for (int t = 0; t < 4; t++) ffma2(accE[e][t], XE[t], Pm[t + e]);

            u64 XO[3] = { pack2(x0.y, x0.z), pack2(x0.w, x1.x), pack2(x1.y, x1.z) };
            // odd dj = 2o+1: px pair (2s+1,2s+2) x q-pair (s+o+1)
            #pragma unroll
            for (int o = 0; o < 4; o++)
                #pragma unroll
                for (int s = 0; s < 3; s++) ffma2(accO[o][s], XO[s], Pm[s + o + 1]);
            // odd edges: px0 uses q[2o+1]; px7 uses q[2o+8]
            aS0[0] = fmaf(x0.x, ya.y, aS0[0]);
            aS0[1] = fmaf(x0.x, ya.w, aS0[1]);
            aS0[2] = fmaf(x0.x, yb.y, aS0[2]);
            aS0[3] = fmaf(x0.x, yb.w, aS0[3]);
            aS7[0] = fmaf(x1.w, yc.x, aS7[0]);
            aS7[1] = fmaf(x1.w, yc.z, aS7[1]);
            aS7[2] = fmaf(x1.w, yd.x, aS7[2]);
            aS7[3] = fmaf(x1.w, yd.z, aS7[3]);
        }
    }

    // ---- epilogue: scale by 1/C, two float4 stores per dj ----
    const float inv = 1.0f / (float)CHAN;
    float* ob = out + (((size_t)b * (PATCH * PATCH) + (size_t)di * PATCH) * H + i) * W + j0;
    #pragma unroll
    for (int dj = 0; dj < PATCH; dj++) {
        float v[8];
        if ((dj & 1) == 0) {
            const int e = dj >> 1;
            #pragma unroll
            for (int t = 0; t < 4; t++) unpack2(accE[e][t], v[2 * t], v[2 * t + 1]);
        } else {
            const int o = dj >> 1;
            v[0] = aS0[o];
            unpack2(accO[o][0], v[1], v[2]);
            unpack2(accO[o][1], v[3], v[4]);
            unpack2(accO[o][2], v[5], v[6]);
            v[7] = aS7[o];
        }
        float4 lo = make_float4(v[0] * inv, v[1] * inv, v[2] * inv, v[3] * inv);
        float4 hi = make_float4(v[4] * inv, v[5] * inv, v[6] * inv, v[7] * inv);
        *reinterpret_cast<float4*>(ob)     = lo;
        *reinterpret_cast<float4*>(ob + 4) = hi;
        ob += HW;
    }
}

extern "C" void kernel_launch(void* const* d_in, const int* in_sizes, int n_in,
                              void* d_out, int out_size)
{
    const float* x = (const float*)d_in[0];
    const float* y = (const float*)d_in[1];
    float* out = (float*)d_out;
    dim3 grid(BATCH * (H / ITILE));   // 256 blocks
    dim3 block(32 * PATCH);           // 288 threads = 9 warps
    corr_kernel<<<grid, block>>>(x, y, out);
}